// round 13
// baseline (speedup 1.0000x reference)
#include <cuda_runtime.h>
#include <cuda_fp16.h>
#include <math.h>
#include <stdint.h>

#define Hh 100
#define Nn 1024
#define Bb 64
#define Ll 16
#define Ej 2048
#define Jn 40000
#define KP 112            // packed K (fp16), zero-padded 100..111
#define RB 224            // bytes per packed B row in global
#define ST 240            // smem row stride (conflict-free: 15*16)
#define JT 128            // j rows per CTA
#define NJT 313
#define SM_A (JT*ST)               // 30720
#define SM_B (64*ST)               // 15360 per buf (2 batches x 32 rows)
#define SM_TOTAL (SM_A + 2*SM_B)   // 61440  -> 3 CTAs/SM

// ---------------- device scratch (no runtime allocs) ----------------
__device__ float g_m[Nn*Hh];
__device__ __align__(16) __half g_cpk[(size_t)Bb*32*KP];    // [b][32][k]
__device__ unsigned g_ctr;                                   // monotonic barrier

__device__ __forceinline__ float sigm(float x) { return 1.0f / (1.0f + __expf(-x)); }

__device__ __forceinline__ uint32_t smem_u32(const void* p) {
    uint32_t a;
    asm("{ .reg .u64 t; cvta.to.shared.u64 t, %1; cvt.u32.u64 %0, t; }" : "=r"(a) : "l"(p));
    return a;
}
__device__ __forceinline__ void cp16(uint32_t dst, const void* src) {
    asm volatile("cp.async.cg.shared.global [%0], [%1], 16;" :: "r"(dst), "l"(src) : "memory");
}
__device__ __forceinline__ void ldsm_x4(uint32_t* r, uint32_t addr) {
    asm volatile("ldmatrix.sync.aligned.m8n8.x4.shared.b16 {%0,%1,%2,%3}, [%4];"
                 : "=r"(r[0]), "=r"(r[1]), "=r"(r[2]), "=r"(r[3]) : "r"(addr));
}
__device__ __forceinline__ void mma16816(float* d, const uint32_t* a, const uint32_t* b) {
    asm volatile(
        "mma.sync.aligned.m16n8k16.row.col.f32.f16.f16.f32 "
        "{%0,%1,%2,%3}, {%4,%5,%6,%7}, {%8,%9}, {%0,%1,%2,%3};"
        : "+f"(d[0]), "+f"(d[1]), "+f"(d[2]), "+f"(d[3])
        : "r"(a[0]), "r"(a[1]), "r"(a[2]), "r"(a[3]), "r"(b[0]), "r"(b[1]));
}

// ================= K0: everything up to coef packing, one block per batch ====
// gather -> m GEMM -> (global barrier) -> local scatter -> GRU -> attn -> pack
__global__ void __launch_bounds__(416) k_all(
    const int* __restrict__ x, const int* __restrict__ ei, const float* __restrict__ ew,
    const float* __restrict__ embed, const float* __restrict__ ggc,
    const float* __restrict__ wih, const float* __restrict__ whh,
    const float* __restrict__ bih, const float* __restrict__ bhh,
    const float* __restrict__ W1w, const float* __restrict__ W1b,
    const float* __restrict__ W2w, const float* __restrict__ W2b,
    const float* __restrict__ Wtw, const float* __restrict__ Wtb,
    const float* __restrict__ qw,  const float* __restrict__ qb,
    const float* __restrict__ W3w, const float* __restrict__ W3b) {
    __shared__ float h_s[Ll*Hh], agg_s[Ll*Hh], v_s[Ll*Hh];
    __shared__ float gi_s[4][300], gh_s[4][300];
    __shared__ float t1[Hh], a_att[Ll*Hh], alpha_s[Ll], sg[Hh], sh_s[Hh];
    __shared__ int list_s[Ej];
    __shared__ int cnt_s;
    int b = blockIdx.x, t = threadIdx.x, nb = b * Ll;

    // ---- gather own 16 nodes; zero agg ----
    for (int i = t; i < Ll * Hh; i += 416) {
        int n = i / Hh, c = i - n * Hh;
        h_s[i] = embed[(size_t)x[nb + n] * Hh + c];
        agg_s[i] = 0.0f;
    }
    if (t == 0) cnt_s = 0;
    __syncthreads();

    // ---- m = h @ ggc -> global ----
    for (int idx = t; idx < Ll * Hh; idx += 416) {
        int n = idx / Hh, k = idx - n * Hh;
        float acc = 0.0f;
        const float* hr = h_s + n * Hh;
        #pragma unroll 4
        for (int c = 0; c < Hh; c++) acc = fmaf(hr[c], ggc[c * Hh + k], acc);
        g_m[(nb + n) * Hh + k] = acc;
    }
    __threadfence();
    __syncthreads();

    // ---- software global barrier (64 co-resident CTAs, monotonic counter) ----
    if (t == 0) {
        unsigned my = atomicAdd(&g_ctr, 1u) + 1u;
        unsigned target = ((my - 1u) / (unsigned)Bb + 1u) * (unsigned)Bb;
        for (;;) {
            unsigned cur;
            asm volatile("ld.volatile.global.u32 %0, [%1];" : "=r"(cur) : "l"(&g_ctr));
            if (cur >= target) break;
            __nanosleep(64);
        }
        __threadfence();
    }
    __syncthreads();

    // ---- local scatter: edges whose dst is in this batch ----
    for (int e = t; e < Ej; e += 416) {
        int d = ei[Ej + e];
        if ((d >> 4) == b) { int p = atomicAdd(&cnt_s, 1); list_s[p] = e; }
    }
    __syncthreads();
    int cnt = cnt_s;
    for (int idx = t; idx < cnt * Hh; idx += 416) {
        int l = idx / Hh, k = idx - l * Hh;
        int e = list_s[l];
        int s = ei[e], dl = ei[Ej + e] - nb;
        atomicAdd(&agg_s[dl * Hh + k], ew[e] * g_m[s * Hh + k]);
    }
    __syncthreads();

    // ---- GRU: 4 groups of 4 nodes ----
    for (int g = 0; g < 4; g++) {
        if (t < 300) {
            float ai0 = bih[t], ai1 = ai0, ai2 = ai0, ai3 = ai0;
            float ah0 = bhh[t], ah1 = ah0, ah2 = ah0, ah3 = ah0;
            const float* a0 = agg_s + (4 * g) * Hh;
            const float* h0 = h_s + (4 * g) * Hh;
            const float* wr = wih + t * Hh;
            const float* ur = whh + t * Hh;
            #pragma unroll 4
            for (int c = 0; c < Hh; c++) {
                float wv = wr[c], uv = ur[c];
                ai0 = fmaf(a0[c],        wv, ai0); ah0 = fmaf(h0[c],        uv, ah0);
                ai1 = fmaf(a0[Hh + c],   wv, ai1); ah1 = fmaf(h0[Hh + c],   uv, ah1);
                ai2 = fmaf(a0[2*Hh + c], wv, ai2); ah2 = fmaf(h0[2*Hh + c], uv, ah2);
                ai3 = fmaf(a0[3*Hh + c], wv, ai3); ah3 = fmaf(h0[3*Hh + c], uv, ah3);
            }
            gi_s[0][t] = ai0; gi_s[1][t] = ai1; gi_s[2][t] = ai2; gi_s[3][t] = ai3;
            gh_s[0][t] = ah0; gh_s[1][t] = ah1; gh_s[2][t] = ah2; gh_s[3][t] = ah3;
        }
        __syncthreads();
        if (t < 400) {
            int n = t / Hh, k = t - n * Hh;
            float r  = sigm(gi_s[n][k]         + gh_s[n][k]);
            float zg = sigm(gi_s[n][Hh + k]    + gh_s[n][Hh + k]);
            float ng = tanhf(gi_s[n][2*Hh + k] + r * gh_s[n][2*Hh + k]);
            v_s[(4 * g + n) * Hh + k] = (1.0f - zg) * ng + zg * h_s[(4 * g + n) * Hh + k];
        }
        __syncthreads();
    }

    // ---- attention readout ----
    if (t < Hh) {
        float acc = W1b[t];
        const float* w = W1w + t * Hh;
        #pragma unroll 4
        for (int c = 0; c < Hh; c++) acc = fmaf(v_s[15 * Hh + c], w[c], acc);
        t1[t] = acc;
    }
    __syncthreads();
    for (int idx = t; idx < Ll * Hh; idx += 416) {
        int l = idx / Hh, k = idx - l * Hh;
        float acc = W2b[k];
        const float* w = W2w + k * Hh;
        const float* vrow = v_s + l * Hh;
        #pragma unroll 4
        for (int c = 0; c < Hh; c++) acc = fmaf(vrow[c], w[c], acc);
        a_att[idx] = sigm(t1[k] + acc);
    }
    __syncthreads();
    if (t < Ll) {
        float acc = qb[0];
        #pragma unroll 4
        for (int k = 0; k < Hh; k++) acc = fmaf(a_att[t * Hh + k], qw[k], acc);
        alpha_s[t] = acc;
    }
    __syncthreads();
    if (t < Hh) {
        float acc = 0.0f;
        #pragma unroll
        for (int l = 0; l < Ll; l++) acc = fmaf(alpha_s[l], v_s[l * Hh + t], acc);
        sg[t] = acc;
    }
    __syncthreads();
    if (t < Hh) {
        float acc = W3b[t];
        const float* w = W3w + t * 2 * Hh;
        #pragma unroll 4
        for (int c = 0; c < Hh; c++)
            acc = fmaf(v_s[15 * Hh + c], w[c], fmaf(sg[c], w[Hh + c], acc));
        sh_s[t] = acc;
    }
    __syncthreads();

    // ---- pack coefs (zero-padded to KP): rows 0-15 = vt, 16-31 = v + sh ----
    for (int idx = t; idx < 32 * KP; idx += 416) {
        int r = idx / KP, k = idx - r * KP;
        float v = 0.0f;
        if (k < Hh) {
            if (r < 16) {
                float acc = Wtb[k];
                const float* w = Wtw + k * Hh;
                const float* vrow = v_s + r * Hh;
                #pragma unroll 4
                for (int c = 0; c < Hh; c++) acc = fmaf(vrow[c], w[c], acc);
                v = acc;
            } else {
                v = v_s[(r - 16) * Hh + k] + sh_s[k];
            }
        }
        g_cpk[((size_t)b * 32 + r) * KP + k] = __float2half(v);
    }
}

// ================= K1: HMMA fused GEMM + softmax epilogue =================
// A built in-kernel from fp32 embed (coalesced float2 -> half2 smem).
__global__ void __launch_bounds__(256, 3) k_ztc(const float* __restrict__ embed,
                                               float* __restrict__ z) {
    extern __shared__ __align__(128) char sm[];
    const uint32_t smA = smem_u32(sm);
    const uint32_t smB = smA + SM_A;
    int tid = threadIdx.x, warp = tid >> 5, lane = tid & 31;
    int wr = warp >> 1, wc = warp & 1;
    int jt = blockIdx.x, bs = blockIdx.y;      // bs: 0..3, 16 batches each

    // kick off B load for bt=0 while converting A
    {
        const char* src = (const char*)g_cpk + (size_t)(bs * 16) * 32 * RB;
        for (int i = tid; i < 64 * 14; i += 256) {
            int r = i / 14, c = i - r * 14;
            cp16(smB + (uint32_t)r * ST + c * 16, src + (size_t)r * RB + c * 16);
        }
    }
    asm volatile("cp.async.commit_group;" ::: "memory");

    // A: load 128 embed rows fp32 (coalesced) -> fp16 smem, zero-pad k 100..111
    {
        const float2* src = (const float2*)(embed + (size_t)jt * JT * Hh);
        int nvalid2 = (min(Jn - jt * JT, JT) * Hh) >> 1;   // 6400 or 3200
        for (int q = tid; q < JT * 50; q += 256) {
            float2 v = (q < nvalid2) ? src[q] : make_float2(0.0f, 0.0f);
            int r = q / 50, pc = q - r * 50;
            *(__half2*)(sm + r * ST + pc * 4) = __floats2half2_rn(v.x, v.y);
        }
        for (int q = tid; q < JT * 6; q += 256) {
            int r = q / 6, pc = 50 + (q - r * 6);
            *(uint32_t*)(sm + r * ST + pc * 4) = 0u;
        }
    }
    asm volatile("cp.async.wait_group 0;" ::: "memory");
    __syncthreads();

    const uint32_t aBase = smA + (uint32_t)(wr * 32 + (lane & 15)) * ST + ((lane >> 4) << 4);
    const uint32_t bOff4 = (uint32_t)(wc * 32 + (lane & 7) + ((lane >> 4) << 3)) * ST
                         + (((lane >> 3) & 1) << 4);

    #pragma unroll 1
    for (int bt = 0; bt < 8; bt++) {
        if (bt + 1 < 8) {
            const char* src = (const char*)g_cpk + (size_t)(bs * 16 + (bt + 1) * 2) * 32 * RB;
            uint32_t dst = smB + (uint32_t)((bt + 1) & 1) * SM_B;
            for (int i = tid; i < 64 * 14; i += 256) {
                int r = i / 14, c = i - r * 14;
                cp16(dst + (uint32_t)r * ST + c * 16, src + (size_t)r * RB + c * 16);
            }
            asm volatile("cp.async.commit_group;" ::: "memory");
        }
        const uint32_t bBase = smB + (uint32_t)(bt & 1) * SM_B + bOff4;

        float acc[2][4][4];
        #pragma unroll
        for (int mt = 0; mt < 2; mt++)
            #pragma unroll
            for (int nt = 0; nt < 4; nt++)
                #pragma unroll
                for (int q = 0; q < 4; q++) acc[mt][nt][q] = 0.0f;

        #pragma unroll
        for (int ksi = 0; ksi < 7; ksi++) {
            uint32_t af[2][4], bf[2][4];
            #pragma unroll
            for (int mt = 0; mt < 2; mt++)
                ldsm_x4(af[mt], aBase + (uint32_t)mt * (16 * ST) + ksi * 32);
            #pragma unroll
            for (int np = 0; np < 2; np++)
                ldsm_x4(bf[np], bBase + (uint32_t)np * (16 * ST) + ksi * 32);
            #pragma unroll
            for (int np = 0; np < 2; np++) {
                #pragma unroll
                for (int mt = 0; mt < 2; mt++) {
                    mma16816(acc[mt][2 * np],     af[mt], bf[np]);
                    mma16816(acc[mt][2 * np + 1], af[mt], bf[np] + 2);
                }
            }
        }

        // epilogue (no max-subtraction: logits bounded, exp safe in fp32)
        int b = bs * 16 + bt * 2 + wc;
        #pragma unroll
        for (int mt = 0; mt < 2; mt++) {
            int jA = jt * JT + wr * 32 + mt * 16 + (lane >> 2);
            #pragma unroll
            for (int half = 0; half < 2; half++) {
                int q0 = half * 2, q1 = half * 2 + 1;
                float e0 = __expf(acc[mt][0][q0]), e1 = __expf(acc[mt][0][q1]);
                float e2 = __expf(acc[mt][1][q0]), e3 = __expf(acc[mt][1][q1]);
                float c0 = acc[mt][2][q0], c1 = acc[mt][2][q1];
                float c2 = acc[mt][3][q0], c3 = acc[mt][3][q1];
                float se = e0 + e1 + e2 + e3;
                float ac = fmaf(e0, c0, fmaf(e1, c1, fmaf(e2, c2, e3 * c3)));
                se += __shfl_xor_sync(0xffffffffu, se, 1);
                ac += __shfl_xor_sync(0xffffffffu, ac, 1);
                se += __shfl_xor_sync(0xffffffffu, se, 2);
                ac += __shfl_xor_sync(0xffffffffu, ac, 2);
                int j = jA + half * 8;
                if ((lane & 3) == 0 && j < Jn)
                    z[(size_t)b * Jn + j] = ac / se;
            }
        }

        if (bt + 1 < 8) asm volatile("cp.async.wait_group 0;" ::: "memory");
        __syncthreads();
    }
}

// ================= launch =================
extern "C" void kernel_launch(void* const* d_in, const int* in_sizes, int n_in,
                              void* d_out, int out_size) {
    const int*   x     = (const int*)  d_in[0];
    const int*   ei    = (const int*)  d_in[1];
    const float* ew    = (const float*)d_in[2];
    const float* embed = (const float*)d_in[4];
    const float* ggc   = (const float*)d_in[5];
    const float* wih   = (const float*)d_in[6];
    const float* whh   = (const float*)d_in[7];
    const float* bih   = (const float*)d_in[8];
    const float* bhh   = (const float*)d_in[9];
    const float* W1w   = (const float*)d_in[10];
    const float* W1b   = (const float*)d_in[11];
    const float* W2w   = (const float*)d_in[12];
    const float* W2b   = (const float*)d_in[13];
    const float* Wtw   = (const float*)d_in[14];
    const float* Wtb   = (const float*)d_in[15];
    const float* qw    = (const float*)d_in[16];
    const float* qb    = (const float*)d_in[17];
    const float* W3w   = (const float*)d_in[18];
    const float* W3b   = (const float*)d_in[19];
    float* z = (float*)d_out;

    cudaFuncSetAttribute(k_ztc, cudaFuncAttributeMaxDynamicSharedMemorySize, SM_TOTAL);

    k_all<<<Bb, 416>>>(x, ei, ew, embed, ggc, wih, whh, bih, bhh,
                       W1w, W1b, W2w, W2b, Wtw, Wtb, qw, qb, W3w, W3b);
    k_ztc<<<dim3(NJT, 4), 256, SM_TOTAL>>>(embed, z);
}

// round 14
// speedup vs baseline: 1.0015x; 1.0015x over previous
#include <cuda_runtime.h>
#include <cuda_fp16.h>
#include <math.h>
#include <stdint.h>

#define Hh 100
#define Nn 1024
#define Bb 64
#define Ll 16
#define Ej 2048
#define Jn 40000
#define KP 112            // packed K (fp16), zero-padded 100..111
#define RB 224            // bytes per packed B row in global
#define ST 240            // smem row stride (conflict-free: 15*16)
#define JT 128            // j rows per CTA
#define NJT 313
#define SM_A (JT*ST)               // 30720
#define SM_B (64*ST)               // 15360 per buf (2 batches x 32 rows)
#define SM_TOTAL (SM_A + 2*SM_B)   // 61440  -> 3 CTAs/SM
#define WSLICE 469                 // 30016/64 weight elems per block

// ---------------- device scratch (no runtime allocs) ----------------
__device__ float g_m[Nn*Hh];
__device__ float g_wihT[Hh*300];   // [c][out] coalesced GRU weights
__device__ float g_whhT[Hh*300];
__device__ __align__(16) __half g_cpk[(size_t)Bb*32*KP];    // [b][32][k]
__device__ unsigned g_ctr;                                   // monotonic barrier

__device__ __forceinline__ float sigm(float x) { return 1.0f / (1.0f + __expf(-x)); }

__device__ __forceinline__ uint32_t smem_u32(const void* p) {
    uint32_t a;
    asm("{ .reg .u64 t; cvta.to.shared.u64 t, %1; cvt.u32.u64 %0, t; }" : "=r"(a) : "l"(p));
    return a;
}
__device__ __forceinline__ void cp16(uint32_t dst, const void* src) {
    asm volatile("cp.async.cg.shared.global [%0], [%1], 16;" :: "r"(dst), "l"(src) : "memory");
}
__device__ __forceinline__ void ldsm_x4(uint32_t* r, uint32_t addr) {
    asm volatile("ldmatrix.sync.aligned.m8n8.x4.shared.b16 {%0,%1,%2,%3}, [%4];"
                 : "=r"(r[0]), "=r"(r[1]), "=r"(r[2]), "=r"(r[3]) : "r"(addr));
}
__device__ __forceinline__ void mma16816(float* d, const uint32_t* a, const uint32_t* b) {
    asm volatile(
        "mma.sync.aligned.m16n8k16.row.col.f32.f16.f16.f32 "
        "{%0,%1,%2,%3}, {%4,%5,%6,%7}, {%8,%9}, {%0,%1,%2,%3};"
        : "+f"(d[0]), "+f"(d[1]), "+f"(d[2]), "+f"(d[3])
        : "r"(a[0]), "r"(a[1]), "r"(a[2]), "r"(a[3]), "r"(b[0]), "r"(b[1]));
}

// ================= K0: everything up to coef packing, one block per batch ====
// gather + m GEMM + weight-transpose slice -> (global barrier) ->
// local scatter -> GRU (coalesced weights) -> attn -> pack
__global__ void __launch_bounds__(416) k_all(
    const int* __restrict__ x, const int* __restrict__ ei, const float* __restrict__ ew,
    const float* __restrict__ embed, const float* __restrict__ ggc,
    const float* __restrict__ wih, const float* __restrict__ whh,
    const float* __restrict__ bih, const float* __restrict__ bhh,
    const float* __restrict__ W1w, const float* __restrict__ W1b,
    const float* __restrict__ W2w, const float* __restrict__ W2b,
    const float* __restrict__ Wtw, const float* __restrict__ Wtb,
    const float* __restrict__ qw,  const float* __restrict__ qb,
    const float* __restrict__ W3w, const float* __restrict__ W3b) {
    __shared__ float h_s[Ll*Hh], agg_s[Ll*Hh], v_s[Ll*Hh];
    __shared__ float gi_s[4][300], gh_s[4][300];
    __shared__ float t1[Hh], a_att[Ll*Hh], alpha_s[Ll], sg[Hh], sh_s[Hh];
    __shared__ int list_s[Ej];
    __shared__ int cnt_s;
    int b = blockIdx.x, t = threadIdx.x, nb = b * Ll;

    // ---- gather own 16 nodes; zero agg ----
    for (int i = t; i < Ll * Hh; i += 416) {
        int n = i / Hh, c = i - n * Hh;
        h_s[i] = embed[(size_t)x[nb + n] * Hh + c];
        agg_s[i] = 0.0f;
    }
    if (t == 0) cnt_s = 0;
    __syncthreads();

    // ---- m = h @ ggc -> global ----
    for (int idx = t; idx < Ll * Hh; idx += 416) {
        int n = idx / Hh, k = idx - n * Hh;
        float acc = 0.0f;
        const float* hr = h_s + n * Hh;
        #pragma unroll 4
        for (int c = 0; c < Hh; c++) acc = fmaf(hr[c], ggc[c * Hh + k], acc);
        g_m[(nb + n) * Hh + k] = acc;
    }
    // ---- transpose this block's slice of GRU weights ----
    {
        int lo = b * WSLICE;
        int hi = lo + WSLICE; if (hi > 300 * Hh) hi = 300 * Hh;
        for (int i = lo + t; i < hi; i += 416) {
            int r = i / Hh, c = i - r * Hh;
            g_wihT[c * 300 + r] = wih[i];
            g_whhT[c * 300 + r] = whh[i];
        }
    }
    __threadfence();
    __syncthreads();

    // ---- software global barrier (64 co-resident CTAs, monotonic counter) ----
    if (t == 0) {
        unsigned my = atomicAdd(&g_ctr, 1u) + 1u;
        unsigned target = ((my - 1u) / (unsigned)Bb + 1u) * (unsigned)Bb;
        for (;;) {
            unsigned cur;
            asm volatile("ld.volatile.global.u32 %0, [%1];" : "=r"(cur) : "l"(&g_ctr));
            if (cur >= target) break;
            __nanosleep(64);
        }
        __threadfence();
    }
    __syncthreads();

    // ---- local scatter: edges whose dst is in this batch ----
    for (int e = t; e < Ej; e += 416) {
        int d = ei[Ej + e];
        if ((d >> 4) == b) { int p = atomicAdd(&cnt_s, 1); list_s[p] = e; }
    }
    __syncthreads();
    int cnt = cnt_s;
    for (int idx = t; idx < cnt * Hh; idx += 416) {
        int l = idx / Hh, k = idx - l * Hh;
        int e = list_s[l];
        int s = ei[e], dl = ei[Ej + e] - nb;
        atomicAdd(&agg_s[dl * Hh + k], ew[e] * g_m[s * Hh + k]);
    }
    __syncthreads();

    // ---- GRU: 4 groups of 4 nodes, coalesced transposed weights ----
    for (int g = 0; g < 4; g++) {
        if (t < 300) {
            float ai0 = bih[t], ai1 = ai0, ai2 = ai0, ai3 = ai0;
            float ah0 = bhh[t], ah1 = ah0, ah2 = ah0, ah3 = ah0;
            const float* a0 = agg_s + (4 * g) * Hh;
            const float* h0 = h_s + (4 * g) * Hh;
            #pragma unroll 4
            for (int c = 0; c < Hh; c++) {
                float wv = g_wihT[c * 300 + t];
                float uv = g_whhT[c * 300 + t];
                ai0 = fmaf(a0[c],        wv, ai0); ah0 = fmaf(h0[c],        uv, ah0);
                ai1 = fmaf(a0[Hh + c],   wv, ai1); ah1 = fmaf(h0[Hh + c],   uv, ah1);
                ai2 = fmaf(a0[2*Hh + c], wv, ai2); ah2 = fmaf(h0[2*Hh + c], uv, ah2);
                ai3 = fmaf(a0[3*Hh + c], wv, ai3); ah3 = fmaf(h0[3*Hh + c], uv, ah3);
            }
            gi_s[0][t] = ai0; gi_s[1][t] = ai1; gi_s[2][t] = ai2; gi_s[3][t] = ai3;
            gh_s[0][t] = ah0; gh_s[1][t] = ah1; gh_s[2][t] = ah2; gh_s[3][t] = ah3;
        }
        __syncthreads();
        if (t < 400) {
            int n = t / Hh, k = t - n * Hh;
            float r  = sigm(gi_s[n][k]         + gh_s[n][k]);
            float zg = sigm(gi_s[n][Hh + k]    + gh_s[n][Hh + k]);
            float ng = tanhf(gi_s[n][2*Hh + k] + r * gh_s[n][2*Hh + k]);
            v_s[(4 * g + n) * Hh + k] = (1.0f - zg) * ng + zg * h_s[(4 * g + n) * Hh + k];
        }
        __syncthreads();
    }

    // ---- attention readout ----
    if (t < Hh) {
        float acc = W1b[t];
        const float* w = W1w + t * Hh;
        #pragma unroll 4
        for (int c = 0; c < Hh; c++) acc = fmaf(v_s[15 * Hh + c], w[c], acc);
        t1[t] = acc;
    }
    __syncthreads();
    for (int idx = t; idx < Ll * Hh; idx += 416) {
        int l = idx / Hh, k = idx - l * Hh;
        float acc = W2b[k];
        const float* w = W2w + k * Hh;
        const float* vrow = v_s + l * Hh;
        #pragma unroll 4
        for (int c = 0; c < Hh; c++) acc = fmaf(vrow[c], w[c], acc);
        a_att[idx] = sigm(t1[k] + acc);
    }
    __syncthreads();
    if (t < Ll) {
        float acc = qb[0];
        #pragma unroll 4
        for (int k = 0; k < Hh; k++) acc = fmaf(a_att[t * Hh + k], qw[k], acc);
        alpha_s[t] = acc;
    }
    __syncthreads();
    if (t < Hh) {
        float acc = 0.0f;
        #pragma unroll
        for (int l = 0; l < Ll; l++) acc = fmaf(alpha_s[l], v_s[l * Hh + t], acc);
        sg[t] = acc;
    }
    __syncthreads();
    if (t < Hh) {
        float acc = W3b[t];
        const float* w = W3w + t * 2 * Hh;
        #pragma unroll 4
        for (int c = 0; c < Hh; c++)
            acc = fmaf(v_s[15 * Hh + c], w[c], fmaf(sg[c], w[Hh + c], acc));
        sh_s[t] = acc;
    }
    __syncthreads();

    // ---- pack coefs (zero-padded to KP): rows 0-15 = vt, 16-31 = v + sh ----
    for (int idx = t; idx < 32 * KP; idx += 416) {
        int r = idx / KP, k = idx - r * KP;
        float v = 0.0f;
        if (k < Hh) {
            if (r < 16) {
                float acc = Wtb[k];
                const float* w = Wtw + k * Hh;
                const float* vrow = v_s + r * Hh;
                #pragma unroll 4
                for (int c = 0; c < Hh; c++) acc = fmaf(vrow[c], w[c], acc);
                v = acc;
            } else {
                v = v_s[(r - 16) * Hh + k] + sh_s[k];
            }
        }
        g_cpk[((size_t)b * 32 + r) * KP + k] = __float2half(v);
    }
}

// ================= K1: HMMA fused GEMM + softmax epilogue =================
// A built in-kernel from fp32 embed (coalesced float2 -> half2 smem).
__global__ void __launch_bounds__(256, 3) k_ztc(const float* __restrict__ embed,
                                               float* __restrict__ z) {
    extern __shared__ __align__(128) char sm[];
    const uint32_t smA = smem_u32(sm);
    const uint32_t smB = smA + SM_A;
    int tid = threadIdx.x, warp = tid >> 5, lane = tid & 31;
    int wr = warp >> 1, wc = warp & 1;
    int jt = blockIdx.x, bs = blockIdx.y;      // bs: 0..3, 16 batches each

    // kick off B load for bt=0 while converting A
    {
        const char* src = (const char*)g_cpk + (size_t)(bs * 16) * 32 * RB;
        for (int i = tid; i < 64 * 14; i += 256) {
            int r = i / 14, c = i - r * 14;
            cp16(smB + (uint32_t)r * ST + c * 16, src + (size_t)r * RB + c * 16);
        }
    }
    asm volatile("cp.async.commit_group;" ::: "memory");

    // A: load 128 embed rows fp32 (coalesced) -> fp16 smem, zero-pad k 100..111
    {
        const float2* src = (const float2*)(embed + (size_t)jt * JT * Hh);
        int nvalid2 = (min(Jn - jt * JT, JT) * Hh) >> 1;
        for (int q = tid; q < JT * 50; q += 256) {
            float2 v = (q < nvalid2) ? src[q] : make_float2(0.0f, 0.0f);
            int r = q / 50, pc = q - r * 50;
            *(__half2*)(sm + r * ST + pc * 4) = __floats2half2_rn(v.x, v.y);
        }
        for (int q = tid; q < JT * 6; q += 256) {
            int r = q / 6, pc = 50 + (q - r * 6);
            *(uint32_t*)(sm + r * ST + pc * 4) = 0u;
        }
    }
    asm volatile("cp.async.wait_group 0;" ::: "memory");
    __syncthreads();

    const uint32_t aBase = smA + (uint32_t)(wr * 32 + (lane & 15)) * ST + ((lane >> 4) << 4);
    const uint32_t bOff4 = (uint32_t)(wc * 32 + (lane & 7) + ((lane >> 4) << 3)) * ST
                         + (((lane >> 3) & 1) << 4);

    #pragma unroll 1
    for (int bt = 0; bt < 8; bt++) {
        if (bt + 1 < 8) {
            const char* src = (const char*)g_cpk + (size_t)(bs * 16 + (bt + 1) * 2) * 32 * RB;
            uint32_t dst = smB + (uint32_t)((bt + 1) & 1) * SM_B;
            for (int i = tid; i < 64 * 14; i += 256) {
                int r = i / 14, c = i - r * 14;
                cp16(dst + (uint32_t)r * ST + c * 16, src + (size_t)r * RB + c * 16);
            }
            asm volatile("cp.async.commit_group;" ::: "memory");
        }
        const uint32_t bBase = smB + (uint32_t)(bt & 1) * SM_B + bOff4;

        float acc[2][4][4];
        #pragma unroll
        for (int mt = 0; mt < 2; mt++)
            #pragma unroll
            for (int nt = 0; nt < 4; nt++)
                #pragma unroll
                for (int q = 0; q < 4; q++) acc[mt][nt][q] = 0.0f;

        #pragma unroll
        for (int ksi = 0; ksi < 7; ksi++) {
            uint32_t af[2][4], bf[2][4];
            #pragma unroll
            for (int mt = 0; mt < 2; mt++)
                ldsm_x4(af[mt], aBase + (uint32_t)mt * (16 * ST) + ksi * 32);
            #pragma unroll
            for (int np = 0; np < 2; np++)
                ldsm_x4(bf[np], bBase + (uint32_t)np * (16 * ST) + ksi * 32);
            #pragma unroll
            for (int np = 0; np < 2; np++) {
                #pragma unroll
                for (int mt = 0; mt < 2; mt++) {
                    mma16816(acc[mt][2 * np],     af[mt], bf[np]);
                    mma16816(acc[mt][2 * np + 1], af[mt], bf[np] + 2);
                }
            }
        }

        // epilogue (no max-subtraction: logits bounded, exp safe in fp32)
        int b = bs * 16 + bt * 2 + wc;
        #pragma unroll
        for (int mt = 0; mt < 2; mt++) {
            int jA = jt * JT + wr * 32 + mt * 16 + (lane >> 2);
            #pragma unroll
            for (int half = 0; half < 2; half++) {
                int q0 = half * 2, q1 = half * 2 + 1;
                float e0 = __expf(acc[mt][0][q0]), e1 = __expf(acc[mt][0][q1]);
                float e2 = __expf(acc[mt][1][q0]), e3 = __expf(acc[mt][1][q1]);
                float c0 = acc[mt][2][q0], c1 = acc[mt][2][q1];
                float c2 = acc[mt][3][q0], c3 = acc[mt][3][q1];
                float se = e0 + e1 + e2 + e3;
                float ac = fmaf(e0, c0, fmaf(e1, c1, fmaf(e2, c2, e3 * c3)));
                se += __shfl_xor_sync(0xffffffffu, se, 1);
                ac += __shfl_xor_sync(0xffffffffu, ac, 1);
                se += __shfl_xor_sync(0xffffffffu, se, 2);
                ac += __shfl_xor_sync(0xffffffffu, ac, 2);
                int j = jA + half * 8;
                if ((lane & 3) == 0 && j < Jn)
                    z[(size_t)b * Jn + j] = ac / se;
            }
        }

        if (bt + 1 < 8) asm volatile("cp.async.wait_group 0;" ::: "memory");
        __syncthreads();
    }
}

// ================= launch =================
extern "C" void kernel_launch(void* const* d_in, const int* in_sizes, int n_in,
                              void* d_out, int out_size) {
    const int*   x     = (const int*)  d_in[0];
    const int*   ei    = (const int*)  d_in[1];
    const float* ew    = (const float*)d_in[2];
    const float* embed = (const float*)d_in[4];
    const float* ggc   = (const float*)d_in[5];
    const float* wih   = (const float*)d_in[6];
    const float* whh   = (const float*)d_in[7];
    const float* bih   = (const float*)d_in[8];
    const float* bhh   = (const float*)d_in[9];
    const float* W1w   = (const float*)d_in[10];
    const float* W1b   = (const float*)d_in[11];
    const float* W2w   = (const float*)d_in[12];
    const float* W2b   = (const float*)d_in[13];
    const float* Wtw   = (const float*)d_in[14];
    const float* Wtb   = (const float*)d_in[15];
    const float* qw    = (const float*)d_in[16];
    const float* qb    = (const float*)d_in[17];
    const float* W3w   = (const float*)d_in[18];
    const float* W3b   = (const float*)d_in[19];
    float* z = (float*)d_out;

    cudaFuncSetAttribute(k_ztc, cudaFuncAttributeMaxDynamicSharedMemorySize, SM_TOTAL);

    k_all<<<Bb, 416>>>(x, ei, ew, embed, ggc, wih, whh, bih, bhh,
                       W1w, W1b, W2w, W2b, Wtw, Wtb, qw, qb, W3w, W3b);
    k_ztc<<<dim3(NJT, 4), 256, SM_TOTAL>>>(embed, z);
}

// round 16
// speedup vs baseline: 1.0065x; 1.0050x over previous
#include <cuda_runtime.h>
#include <cuda_fp16.h>
#include <math.h>
#include <stdint.h>

#define Hh 100
#define Nn 1024
#define Bb 64
#define Ll 16
#define Ej 2048
#define Jn 40000
#define KP 112            // packed K (fp16), zero-padded 100..111
#define RB 224            // bytes per packed B row in global
#define ST 240            // smem row stride (conflict-free: 15*16)
#define JT 128            // j rows per CTA
#define NJT 313
#define SM_A (JT*ST)               // 30720
#define SM_B (64*ST)               // 15360 per buf (2 batches x 32 rows)
#define SM_TOTAL (SM_A + 2*SM_B)   // 61440  -> 3 CTAs/SM
#define WSLICE 469                 // 30016/64 weight elems per block

// ---------------- device scratch (no runtime allocs) ----------------
__device__ float g_m[Nn*Hh];
__device__ float g_wihT[Hh*300];   // [c][out] coalesced GRU weights
__device__ float g_whhT[Hh*300];
__device__ __align__(16) __half g_cpk[(size_t)Bb*32*KP];    // [b][32][k]
__device__ unsigned g_ctr;                                   // monotonic barrier

__device__ __forceinline__ float sigm(float x) { return 1.0f / (1.0f + __expf(-x)); }

__device__ __forceinline__ uint32_t smem_u32(const void* p) {
    uint32_t a;
    asm("{ .reg .u64 t; cvta.to.shared.u64 t, %1; cvt.u32.u64 %0, t; }" : "=r"(a) : "l"(p));
    return a;
}
__device__ __forceinline__ void cp16(uint32_t dst, const void* src) {
    asm volatile("cp.async.cg.shared.global [%0], [%1], 16;" :: "r"(dst), "l"(src) : "memory");
}
__device__ __forceinline__ void ldsm_x4(uint32_t* r, uint32_t addr) {
    asm volatile("ldmatrix.sync.aligned.m8n8.x4.shared.b16 {%0,%1,%2,%3}, [%4];"
                 : "=r"(r[0]), "=r"(r[1]), "=r"(r[2]), "=r"(r[3]) : "r"(addr));
}
__device__ __forceinline__ void mma16816(float* d, const uint32_t* a, const uint32_t* b) {
    asm volatile(
        "mma.sync.aligned.m16n8k16.row.col.f32.f16.f16.f32 "
        "{%0,%1,%2,%3}, {%4,%5,%6,%7}, {%8,%9}, {%0,%1,%2,%3};"
        : "+f"(d[0]), "+f"(d[1]), "+f"(d[2]), "+f"(d[3])
        : "r"(a[0]), "r"(a[1]), "r"(a[2]), "r"(a[3]), "r"(b[0]), "r"(b[1]));
}

// ================= K0: everything up to coef packing, one block per batch ====
// gather + m GEMM + weight-transpose slice -> (global barrier) ->
// local scatter -> GRU (coalesced weights) -> attn -> pack
__global__ void __launch_bounds__(416) k_all(
    const int* __restrict__ x, const int* __restrict__ ei, const float* __restrict__ ew,
    const float* __restrict__ embed, const float* __restrict__ ggc,
    const float* __restrict__ wih, const float* __restrict__ whh,
    const float* __restrict__ bih, const float* __restrict__ bhh,
    const float* __restrict__ W1w, const float* __restrict__ W1b,
    const float* __restrict__ W2w, const float* __restrict__ W2b,
    const float* __restrict__ Wtw, const float* __restrict__ Wtb,
    const float* __restrict__ qw,  const float* __restrict__ qb,
    const float* __restrict__ W3w, const float* __restrict__ W3b) {
    __shared__ float h_s[Ll*Hh], agg_s[Ll*Hh], v_s[Ll*Hh];
    __shared__ float gi_s[4][300], gh_s[4][300];
    __shared__ float t1[Hh], a_att[Ll*Hh], alpha_s[Ll], sg[Hh], sh_s[Hh];
    __shared__ int list_s[Ej];
    __shared__ int cnt_s;
    int b = blockIdx.x, t = threadIdx.x, nb = b * Ll;

    // ---- gather own 16 nodes; zero agg ----
    for (int i = t; i < Ll * Hh; i += 416) {
        int n = i / Hh, c = i - n * Hh;
        h_s[i] = embed[(size_t)x[nb + n] * Hh + c];
        agg_s[i] = 0.0f;
    }
    if (t == 0) cnt_s = 0;
    __syncthreads();

    // ---- m = h @ ggc -> global ----
    for (int idx = t; idx < Ll * Hh; idx += 416) {
        int n = idx / Hh, k = idx - n * Hh;
        float acc = 0.0f;
        const float* hr = h_s + n * Hh;
        #pragma unroll 4
        for (int c = 0; c < Hh; c++) acc = fmaf(hr[c], ggc[c * Hh + k], acc);
        g_m[(nb + n) * Hh + k] = acc;
    }
    // ---- transpose this block's slice of GRU weights ----
    {
        int lo = b * WSLICE;
        int hi = lo + WSLICE; if (hi > 300 * Hh) hi = 300 * Hh;
        for (int i = lo + t; i < hi; i += 416) {
            int r = i / Hh, c = i - r * Hh;
            g_wihT[c * 300 + r] = wih[i];
            g_whhT[c * 300 + r] = whh[i];
        }
    }
    __threadfence();
    __syncthreads();

    // ---- software global barrier (64 co-resident CTAs, monotonic counter) ----
    if (t == 0) {
        unsigned my = atomicAdd(&g_ctr, 1u) + 1u;
        unsigned target = ((my - 1u) / (unsigned)Bb + 1u) * (unsigned)Bb;
        for (;;) {
            unsigned cur;
            asm volatile("ld.volatile.global.u32 %0, [%1];" : "=r"(cur) : "l"(&g_ctr));
            if (cur >= target) break;
            __nanosleep(64);
        }
        __threadfence();
    }
    __syncthreads();

    // ---- local scatter: edges whose dst is in this batch ----
    for (int e = t; e < Ej; e += 416) {
        int d = ei[Ej + e];
        if ((d >> 4) == b) { int p = atomicAdd(&cnt_s, 1); list_s[p] = e; }
    }
    __syncthreads();
    int cnt = cnt_s;
    for (int idx = t; idx < cnt * Hh; idx += 416) {
        int l = idx / Hh, k = idx - l * Hh;
        int e = list_s[l];
        int s = ei[e], dl = ei[Ej + e] - nb;
        atomicAdd(&agg_s[dl * Hh + k], ew[e] * g_m[s * Hh + k]);
    }
    __syncthreads();

    // ---- GRU: 4 groups of 4 nodes, coalesced transposed weights ----
    for (int g = 0; g < 4; g++) {
        if (t < 300) {
            float ai0 = bih[t], ai1 = ai0, ai2 = ai0, ai3 = ai0;
            float ah0 = bhh[t], ah1 = ah0, ah2 = ah0, ah3 = ah0;
            const float* a0 = agg_s + (4 * g) * Hh;
            const float* h0 = h_s + (4 * g) * Hh;
            #pragma unroll 4
            for (int c = 0; c < Hh; c++) {
                float wv = g_wihT[c * 300 + t];
                float uv = g_whhT[c * 300 + t];
                ai0 = fmaf(a0[c],        wv, ai0); ah0 = fmaf(h0[c],        uv, ah0);
                ai1 = fmaf(a0[Hh + c],   wv, ai1); ah1 = fmaf(h0[Hh + c],   uv, ah1);
                ai2 = fmaf(a0[2*Hh + c], wv, ai2); ah2 = fmaf(h0[2*Hh + c], uv, ah2);
                ai3 = fmaf(a0[3*Hh + c], wv, ai3); ah3 = fmaf(h0[3*Hh + c], uv, ah3);
            }
            gi_s[0][t] = ai0; gi_s[1][t] = ai1; gi_s[2][t] = ai2; gi_s[3][t] = ai3;
            gh_s[0][t] = ah0; gh_s[1][t] = ah1; gh_s[2][t] = ah2; gh_s[3][t] = ah3;
        }
        __syncthreads();
        if (t < 400) {
            int n = t / Hh, k = t - n * Hh;
            float r  = sigm(gi_s[n][k]         + gh_s[n][k]);
            float zg = sigm(gi_s[n][Hh + k]    + gh_s[n][Hh + k]);
            float ng = tanhf(gi_s[n][2*Hh + k] + r * gh_s[n][2*Hh + k]);
            v_s[(4 * g + n) * Hh + k] = (1.0f - zg) * ng + zg * h_s[(4 * g + n) * Hh + k];
        }
        __syncthreads();
    }

    // ---- attention readout ----
    if (t < Hh) {
        float acc = W1b[t];
        const float* w = W1w + t * Hh;
        #pragma unroll 4
        for (int c = 0; c < Hh; c++) acc = fmaf(v_s[15 * Hh + c], w[c], acc);
        t1[t] = acc;
    }
    __syncthreads();
    for (int idx = t; idx < Ll * Hh; idx += 416) {
        int l = idx / Hh, k = idx - l * Hh;
        float acc = W2b[k];
        const float* w = W2w + k * Hh;
        const float* vrow = v_s + l * Hh;
        #pragma unroll 4
        for (int c = 0; c < Hh; c++) acc = fmaf(vrow[c], w[c], acc);
        a_att[idx] = sigm(t1[k] + acc);
    }
    __syncthreads();
    if (t < Ll) {
        float acc = qb[0];
        #pragma unroll 4
        for (int k = 0; k < Hh; k++) acc = fmaf(a_att[t * Hh + k], qw[k], acc);
        alpha_s[t] = acc;
    }
    __syncthreads();
    if (t < Hh) {
        float acc = 0.0f;
        #pragma unroll
        for (int l = 0; l < Ll; l++) acc = fmaf(alpha_s[l], v_s[l * Hh + t], acc);
        sg[t] = acc;
    }
    __syncthreads();
    if (t < Hh) {
        float acc = W3b[t];
        const float* w = W3w + t * 2 * Hh;
        #pragma unroll 4
        for (int c = 0; c < Hh; c++)
            acc = fmaf(v_s[15 * Hh + c], w[c], fmaf(sg[c], w[Hh + c], acc));
        sh_s[t] = acc;
    }
    __syncthreads();

    // ---- pack coefs (zero-padded to KP): rows 0-15 = vt, 16-31 = v + sh ----
    for (int idx = t; idx < 32 * KP; idx += 416) {
        int r = idx / KP, k = idx - r * KP;
        float v = 0.0f;
        if (k < Hh) {
            if (r < 16) {
                float acc = Wtb[k];
                const float* w = Wtw + k * Hh;
                const float* vrow = v_s + r * Hh;
                #pragma unroll 4
                for (int c = 0; c < Hh; c++) acc = fmaf(vrow[c], w[c], acc);
                v = acc;
            } else {
                v = v_s[(r - 16) * Hh + k] + sh_s[k];
            }
        }
        g_cpk[((size_t)b * 32 + r) * KP + k] = __float2half(v);
    }
}

// ================= K1: HMMA fused GEMM + softmax epilogue =================
// A built in-kernel from fp32 embed (coalesced float2 -> half2 smem).
__global__ void __launch_bounds__(256, 3) k_ztc(const float* __restrict__ embed,
                                               float* __restrict__ z) {
    extern __shared__ __align__(128) char sm[];
    const uint32_t smA = smem_u32(sm);
    const uint32_t smB = smA + SM_A;
    int tid = threadIdx.x, warp = tid >> 5, lane = tid & 31;
    int wr = warp >> 1, wc = warp & 1;
    int jt = blockIdx.x, bs = blockIdx.y;      // bs: 0..3, 16 batches each

    // kick off B load for bt=0 while converting A
    {
        const char* src = (const char*)g_cpk + (size_t)(bs * 16) * 32 * RB;
        for (int i = tid; i < 64 * 14; i += 256) {
            int r = i / 14, c = i - r * 14;
            cp16(smB + (uint32_t)r * ST + c * 16, src + (size_t)r * RB + c * 16);
        }
    }
    asm volatile("cp.async.commit_group;" ::: "memory");

    // A: load 128 embed rows fp32 (coalesced) -> fp16 smem, zero-pad k 100..111
    {
        const float2* src = (const float2*)(embed + (size_t)jt * JT * Hh);
        int nvalid2 = (min(Jn - jt * JT, JT) * Hh) >> 1;
        for (int q = tid; q < JT * 50; q += 256) {
            float2 v = (q < nvalid2) ? src[q] : make_float2(0.0f, 0.0f);
            int r = q / 50, pc = q - r * 50;
            *(__half2*)(sm + r * ST + pc * 4) = __floats2half2_rn(v.x, v.y);
        }
        for (int q = tid; q < JT * 6; q += 256) {
            int r = q / 6, pc = 50 + (q - r * 6);
            *(uint32_t*)(sm + r * ST + pc * 4) = 0u;
        }
    }
    asm volatile("cp.async.wait_group 0;" ::: "memory");
    __syncthreads();

    const uint32_t aBase = smA + (uint32_t)(wr * 32 + (lane & 15)) * ST + ((lane >> 4) << 4);
    const uint32_t bOff4 = (uint32_t)(wc * 32 + (lane & 7) + ((lane >> 4) << 3)) * ST
                         + (((lane >> 3) & 1) << 4);

    #pragma unroll 1
    for (int bt = 0; bt < 8; bt++) {
        if (bt + 1 < 8) {
            const char* src = (const char*)g_cpk + (size_t)(bs * 16 + (bt + 1) * 2) * 32 * RB;
            uint32_t dst = smB + (uint32_t)((bt + 1) & 1) * SM_B;
            for (int i = tid; i < 64 * 14; i += 256) {
                int r = i / 14, c = i - r * 14;
                cp16(dst + (uint32_t)r * ST + c * 16, src + (size_t)r * RB + c * 16);
            }
            asm volatile("cp.async.commit_group;" ::: "memory");
        }
        const uint32_t bBase = smB + (uint32_t)(bt & 1) * SM_B + bOff4;

        float acc[2][4][4];
        #pragma unroll
        for (int mt = 0; mt < 2; mt++)
            #pragma unroll
            for (int nt = 0; nt < 4; nt++)
                #pragma unroll
                for (int q = 0; q < 4; q++) acc[mt][nt][q] = 0.0f;

        #pragma unroll
        for (int ksi = 0; ksi < 7; ksi++) {
            uint32_t af[2][4], bf[2][4];
            #pragma unroll
            for (int mt = 0; mt < 2; mt++)
                ldsm_x4(af[mt], aBase + (uint32_t)mt * (16 * ST) + ksi * 32);
            #pragma unroll
            for (int np = 0; np < 2; np++)
                ldsm_x4(bf[np], bBase + (uint32_t)np * (16 * ST) + ksi * 32);
            #pragma unroll
            for (int np = 0; np < 2; np++) {
                #pragma unroll
                for (int mt = 0; mt < 2; mt++) {
                    mma16816(acc[mt][2 * np],     af[mt], bf[np]);
                    mma16816(acc[mt][2 * np + 1], af[mt], bf[np] + 2);
                }
            }
        }

        // epilogue (no max-subtraction: logits bounded, exp safe in fp32)
        int b = bs * 16 + bt * 2 + wc;
        #pragma unroll
        for (int mt = 0; mt < 2; mt++) {
            int jA = jt * JT + wr * 32 + mt * 16 + (lane >> 2);
            #pragma unroll
            for (int half = 0; half < 2; half++) {
                int q0 = half * 2, q1 = half * 2 + 1;
                float e0 = __expf(acc[mt][0][q0]), e1 = __expf(acc[mt][0][q1]);
                float e2 = __expf(acc[mt][1][q0]), e3 = __expf(acc[mt][1][q1]);
                float c0 = acc[mt][2][q0], c1 = acc[mt][2][q1];
                float c2 = acc[mt][3][q0], c3 = acc[mt][3][q1];
                float se = e0 + e1 + e2 + e3;
                float ac = fmaf(e0, c0, fmaf(e1, c1, fmaf(e2, c2, e3 * c3)));
                se += __shfl_xor_sync(0xffffffffu, se, 1);
                ac += __shfl_xor_sync(0xffffffffu, ac, 1);
                se += __shfl_xor_sync(0xffffffffu, se, 2);
                ac += __shfl_xor_sync(0xffffffffu, ac, 2);
                int j = jA + half * 8;
                if ((lane & 3) == 0 && j < Jn)
                    z[(size_t)b * Jn + j] = ac / se;
            }
        }

        if (bt + 1 < 8) asm volatile("cp.async.wait_group 0;" ::: "memory");
        __syncthreads();
    }
}

// ================= launch =================
extern "C" void kernel_launch(void* const* d_in, const int* in_sizes, int n_in,
                              void* d_out, int out_size) {
    const int*   x     = (const int*)  d_in[0];
    const int*   ei    = (const int*)  d_in[1];
    const float* ew    = (const float*)d_in[2];
    const float* embed = (const float*)d_in[4];
    const float* ggc   = (const float*)d_in[5];
    const float* wih   = (const float*)d_in[6];
    const float* whh   = (const float*)d_in[7];
    const float* bih   = (const float*)d_in[8];
    const float* bhh   = (const float*)d_in[9];
    const float* W1w   = (const float*)d_in[10];
    const float* W1b   = (const float*)d_in[11];
    const float* W2w   = (const float*)d_in[12];
    const float* W2b   = (const float*)d_in[13];
    const float* Wtw   = (const float*)d_in[14];
    const float* Wtb   = (const float*)d_in[15];
    const float* qw    = (const float*)d_in[16];
    const float* qb    = (const float*)d_in[17];
    const float* W3w   = (const float*)d_in[18];
    const float* W3b   = (const float*)d_in[19];
    float* z = (float*)d_out;

    cudaFuncSetAttribute(k_ztc, cudaFuncAttributeMaxDynamicSharedMemorySize, SM_TOTAL);

    k_all<<<Bb, 416>>>(x, ei, ew, embed, ggc, wih, whh, bih, bhh,
                       W1w, W1b, W2w, W2b, Wtw, Wtb, qw, qb, W3w, W3b);
    k_ztc<<<dim3(NJT, 4), 256, SM_TOTAL>>>(embed, z);
}